// round 13
// baseline (speedup 1.0000x reference)
#include <cuda_runtime.h>
#include <cstdint>

#define N_NODES 20000
#define N_EDGES 320000

typedef unsigned long long u64;

// ---------------- device scratch -----------------------------------------------
__device__ __align__(16) float g_h[N_NODES * 64];               // h = nf@w_up/8
__device__ __align__(16) float g_agg[(size_t)N_NODES * 576];    // m-major planes
__device__ __align__(16) uint32_t g_wsplit[22592];              // pre-split MLP weights
__device__ int   g_cnt[N_NODES];                                // histogram -> cursor
__device__ int   g_rowptr[N_NODES + 1];
__device__ int   g_perm[N_EDGES];
__device__ __align__(16) float g_msg[(size_t)N_EDGES * 192];    // 245.8 MB factored msgs
__device__ __align__(16) float g_y[(size_t)N_EDGES * 8];        // per-edge SH (y1:3, y2:5)

// ---------------- helpers -------------------------------------------------------
__device__ __forceinline__ uint32_t packbf(float lo, float hi) {
    uint32_t d; asm("cvt.rn.bf16x2.f32 %0, %1, %2;" : "=r"(d) : "f"(hi), "f"(lo));
    return d;
}
__device__ __forceinline__ uint2 split_pair(float v0, float v1) {
    uint32_t h = packbf(v0, v1);
    float l0 = v0 - __uint_as_float(h << 16);
    float l1 = v1 - __uint_as_float(h & 0xFFFF0000u);
    return make_uint2(h, packbf(l0, l1));
}
#define MMA16(C, a0, a1, a2, a3, b0, b1) \
    asm volatile("mma.sync.aligned.m16n8k16.row.col.f32.bf16.bf16.f32 " \
        "{%0,%1,%2,%3}, {%4,%5,%6,%7}, {%8,%9}, {%0,%1,%2,%3};" \
        : "+f"((C)[0]), "+f"((C)[1]), "+f"((C)[2]), "+f"((C)[3]) \
        : "r"(a0), "r"(a1), "r"(a2), "r"(a3), "r"(b0), "r"(b1))
#define MMA8B(C, a0, a1, b0) \
    asm volatile("mma.sync.aligned.m16n8k8.row.col.f32.bf16.bf16.f32 " \
        "{%0,%1,%2,%3}, {%4,%5}, {%6}, {%0,%1,%2,%3};" \
        : "+f"((C)[0]), "+f"((C)[1]), "+f"((C)[2]), "+f"((C)[3]) \
        : "r"(a0), "r"(a1), "r"(b0))

// 3-term bf16-split MMA over K=64 from register A-fragments, smem weights.
__device__ __forceinline__ void mma_layer_reg(const uint32_t* __restrict__ aH,
                                              const uint32_t* __restrict__ aL,
                                              const uint32_t* __restrict__ wHi,
                                              const uint32_t* __restrict__ wLo,
                                              int ws, int nbase, float C[8][4],
                                              int lane) {
    const int g = lane >> 2, q = lane & 3;
#pragma unroll
    for (int nt = 0; nt < 8; nt++)
        C[nt][0] = C[nt][1] = C[nt][2] = C[nt][3] = 0.f;
#pragma unroll
    for (int kt = 0; kt < 4; kt++) {
        uint32_t ah0 = aH[kt * 4 + 0], ah1 = aH[kt * 4 + 1];
        uint32_t ah2 = aH[kt * 4 + 2], ah3 = aH[kt * 4 + 3];
        uint32_t al0 = aL[kt * 4 + 0], al1 = aL[kt * 4 + 1];
        uint32_t al2 = aL[kt * 4 + 2], al3 = aL[kt * 4 + 3];
        const int b0r = (kt * 8 + q) * ws;
        const int b1r = (kt * 8 + 4 + q) * ws;
#pragma unroll
        for (int nt = 0; nt < 8; nt++) {
            const int n = nbase + nt * 8 + g;
            uint32_t bh0 = wHi[b0r + n], bh1 = wHi[b1r + n];
            uint32_t bl0 = wLo[b0r + n], bl1 = wLo[b1r + n];
            MMA16(C[nt], ah0, ah1, ah2, ah3, bh0, bh1);
            MMA16(C[nt], ah0, ah1, ah2, ah3, bl0, bl1);
            MMA16(C[nt], al0, al1, al2, al3, bh0, bh1);
        }
    }
}

// ---------------- init: zero histogram + node_up + weight prep ------------------
__device__ __forceinline__ void fill_dev(const float* __restrict__ w,
                                         uint32_t* __restrict__ dHi,
                                         uint32_t* __restrict__ dLo,
                                         int K2, int N, int ws, int t) {
    for (int i = t; i < K2 * N; i += 256) {
        int k2 = i / N, n = i - k2 * N;
        uint2 p = split_pair(w[(2 * k2) * N + n], w[(2 * k2 + 1) * N + n]);
        dHi[k2 * ws + n] = p.x;
        dLo[k2 * ws + n] = p.y;
    }
}

__global__ void __launch_bounds__(256) k_init(
    const float* __restrict__ nf, const float* __restrict__ wup,
    const float* __restrict__ w1, const float* __restrict__ w2,
    const float* __restrict__ w3, const float* __restrict__ w4) {
    __shared__ __align__(16) float sW[64 * 64];
    __shared__ float sA[32 * 65];
    const int b = blockIdx.x;
    const int t = threadIdx.x;

    if (b < 79) {                          // zero receiver histogram
        int i = b * 256 + t;
        if (i < N_NODES) g_cnt[i] = 0;
    } else if (b < 704) {                  // h = nf @ w_up * (1/8)
        const int nb = (b - 79) * 32;
        for (int i = t; i < 4096; i += 256) sW[i] = wup[i];
        for (int i = t; i < 2048; i += 256) sA[(i >> 6) * 65 + (i & 63)] = nf[nb * 64 + i];
        __syncthreads();
        const int ty = t >> 4, tx = t & 15;
        const int r0 = ty * 2, c0 = tx * 4;
        float acc[2][4] = {};
#pragma unroll 8
        for (int k = 0; k < 64; k++) {
            float a0 = sA[r0 * 65 + k];
            float a1 = sA[(r0 + 1) * 65 + k];
            float4 bb = *reinterpret_cast<const float4*>(&sW[k * 64 + c0]);
            acc[0][0] += a0 * bb.x; acc[0][1] += a0 * bb.y; acc[0][2] += a0 * bb.z; acc[0][3] += a0 * bb.w;
            acc[1][0] += a1 * bb.x; acc[1][1] += a1 * bb.y; acc[1][2] += a1 * bb.z; acc[1][3] += a1 * bb.w;
        }
#pragma unroll
        for (int i = 0; i < 2; i++)
#pragma unroll
            for (int j = 0; j < 4; j++)
                g_h[(nb + r0 + i) * 64 + c0 + j] = acc[i][j] * 0.125f;
    } else {                               // pre-split MLP weights
        const int bb = b - 704;
        if (bb == 0)      fill_dev(w1, g_wsplit,        g_wsplit + 288,   4,  64,  72,  t);
        else if (bb == 1) fill_dev(w2, g_wsplit + 576,  g_wsplit + 2880,  32, 64,  72,  t);
        else if (bb == 2) fill_dev(w3, g_wsplit + 5184, g_wsplit + 7488,  32, 64,  72,  t);
        else              fill_dev(w4, g_wsplit + 9792, g_wsplit + 16192, 32, 192, 200, t);
    }
}

// ---------------- CSR build: histogram -> scan -> rank --------------------------
__global__ void __launch_bounds__(256) k_hist(const int* __restrict__ receivers) {
    int e = blockIdx.x * 256 + threadIdx.x;
    atomicAdd(&g_cnt[receivers[e]], 1);
}

__global__ void __launch_bounds__(1024) k_scan() {   // single block
    __shared__ int part[1024];
    const int t = threadIdx.x;
    const int base = t * 20;
    int loc[20];
    int s = 0;
#pragma unroll
    for (int j = 0; j < 20; j++) {
        int idx = base + j;
        int v = (idx < N_NODES) ? g_cnt[idx] : 0;
        loc[j] = s; s += v;
    }
    part[t] = s;
    __syncthreads();
    for (int off = 1; off < 1024; off <<= 1) {
        int v = (t >= off) ? part[t - off] : 0;
        __syncthreads();
        part[t] += v;
        __syncthreads();
    }
    int pre = (t == 0) ? 0 : part[t - 1];
#pragma unroll
    for (int j = 0; j < 20; j++) {
        int idx = base + j;
        if (idx < N_NODES) {
            int p = pre + loc[j];
            g_rowptr[idx] = p;
            g_cnt[idx]    = p;      // cursor init
        }
    }
    if (t == 1023) g_rowptr[N_NODES] = N_EDGES;
}

__global__ void __launch_bounds__(256) k_rank(const int* __restrict__ receivers) {
    int e = blockIdx.x * 256 + threadIdx.x;
    int pos = atomicAdd(&g_cnt[receivers[e]], 1);
    g_perm[pos] = e;
}

// ---------------- fused MLP -> factored message store (NO atomics) --------------
__device__ __forceinline__ void act_frags(const float C[8][4], float scale,
                                          uint32_t* __restrict__ aH,
                                          uint32_t* __restrict__ aL) {
    float v[8][4];
#pragma unroll
    for (int nt = 0; nt < 8; nt++)
#pragma unroll
        for (int j = 0; j < 4; j++) {
            float x = C[nt][j] * scale;
            v[nt][j] = __fdividef(x, 1.f + __expf(-x));
        }
#pragma unroll
    for (int kt = 0; kt < 4; kt++) {
        uint2 p0 = split_pair(v[2 * kt][0],     v[2 * kt][1]);
        uint2 p1 = split_pair(v[2 * kt][2],     v[2 * kt][3]);
        uint2 p2 = split_pair(v[2 * kt + 1][0], v[2 * kt + 1][1]);
        uint2 p3 = split_pair(v[2 * kt + 1][2], v[2 * kt + 1][3]);
        aH[kt * 4 + 0] = p0.x; aL[kt * 4 + 0] = p0.y;
        aH[kt * 4 + 1] = p1.x; aL[kt * 4 + 1] = p1.y;
        aH[kt * 4 + 2] = p2.x; aL[kt * 4 + 2] = p2.y;
        aH[kt * 4 + 3] = p3.x; aL[kt * 4 + 3] = p3.y;
    }
}

__global__ void __launch_bounds__(256, 2) k_fused(
    const float* __restrict__ radial, const float* __restrict__ vectors,
    const int* __restrict__ senders) {
    extern __shared__ __align__(16) uint32_t smu[];
    uint32_t* wHi1 = smu;            uint32_t* wLo1 = smu + 288;
    uint32_t* wHi2 = smu + 576;      uint32_t* wLo2 = smu + 2880;
    uint32_t* wHi3 = smu + 5184;     uint32_t* wLo3 = smu + 7488;
    uint32_t* wHi4 = smu + 9792;     uint32_t* wLo4 = smu + 16192;

    const int t    = threadIdx.x;
    const int warp = t >> 5;
    const int lane = t & 31;
    const int w16  = warp * 16;
    const int g = lane >> 2, q = lane & 3;

    // flat copy of pre-split weights (22592 u32 = 5648 uint4)
    {
        const uint4* src = reinterpret_cast<const uint4*>(g_wsplit);
        uint4*       dst = reinterpret_cast<uint4*>(smu);
        for (int i = t; i < 5648; i += 256) dst[i] = src[i];
    }

    // sorted slots i0/i1 -> original edges e0/e1 (hoisted loads)
    const int i0 = blockIdx.x * 128 + w16 + g;
    const int i1 = i0 + 8;
    const int e0 = g_perm[i0];
    const int e1 = g_perm[i1];
    const int snd0 = senders[e0], snd1 = senders[e1];
    float vxa = vectors[(size_t)e0 * 3 + 0];
    float vya = vectors[(size_t)e0 * 3 + 1];
    float vza = vectors[(size_t)e0 * 3 + 2];
    float vxb = vectors[(size_t)e1 * 3 + 0];
    float vyb = vectors[(size_t)e1 * 3 + 1];
    float vzb = vectors[(size_t)e1 * 3 + 2];

    __syncthreads();

    float C[8][4];
    uint32_t aH[16], aL[16];

    // ---- layer 1: radial rows (gathered via perm) @ W1, scale 1/sqrt(8), silu ----
    {
        const float* rA = radial + (size_t)e0 * 8;
        const float* rB = radial + (size_t)e1 * 8;
        float2 q0 = *reinterpret_cast<const float2*>(rA + 2 * q);
        float2 q1 = *reinterpret_cast<const float2*>(rB + 2 * q);
        uint2 a0 = split_pair(q0.x, q0.y);
        uint2 a1 = split_pair(q1.x, q1.y);
#pragma unroll
        for (int nt = 0; nt < 8; nt++) {
            C[nt][0] = C[nt][1] = C[nt][2] = C[nt][3] = 0.f;
            const int n = nt * 8 + g;
            uint32_t bh = wHi1[q * 72 + n];
            uint32_t bl = wLo1[q * 72 + n];
            MMA8B(C[nt], a0.x, a1.x, bh);
            MMA8B(C[nt], a0.x, a1.x, bl);
            MMA8B(C[nt], a0.y, a1.y, bh);
        }
        act_frags(C, 0.35355339059327373f, aH, aL);
    }

    // ---- layer 2 ----
    mma_layer_reg(aH, aL, wHi2, wLo2, 72, 0, C, lane);
    act_frags(C, 0.125f, aH, aL);

    // ---- h gathers hide under layer 3 ----
    float2 hA[8], hB[8];
#pragma unroll
    for (int nt = 0; nt < 8; nt++) {
        hA[nt] = *reinterpret_cast<const float2*>(g_h + (size_t)snd0 * 64 + nt * 8 + 2 * q);
        hB[nt] = *reinterpret_cast<const float2*>(g_h + (size_t)snd1 * 64 + nt * 8 + 2 * q);
    }

    // ---- layer 3 ----
    mma_layer_reg(aH, aL, wHi3, wLo3, 72, 0, C, lane);
    act_frags(C, 0.125f, aH, aL);

    // ---- spherical harmonics -> g_y (q0 stores edge A, q1 stores edge B) ----
    {
        float rn = rsqrtf(vxa * vxa + vya * vya + vza * vza);
        float x = vxa * rn, y = vya * rn, z = vza * rn;
        const float SQ3 = 1.7320508075688772f, S15 = 3.872983346207417f;
        float4 ya0 = make_float4(SQ3 * x, SQ3 * y, SQ3 * z, S15 * x * y);
        float4 ya1 = make_float4(S15 * y * z, 1.118033988749895f * (3.f * z * z - 1.f),
                                 S15 * x * z, 0.5f * S15 * (x * x - y * y));
        if (q == 0) {
            *reinterpret_cast<float4*>(g_y + (size_t)i0 * 8)     = ya0;
            *reinterpret_cast<float4*>(g_y + (size_t)i0 * 8 + 4) = ya1;
        }
    }
    {
        float rn = rsqrtf(vxb * vxb + vyb * vyb + vzb * vzb);
        float x = vxb * rn, y = vyb * rn, z = vzb * rn;
        const float SQ3 = 1.7320508075688772f, S15 = 3.872983346207417f;
        float4 yb0 = make_float4(SQ3 * x, SQ3 * y, SQ3 * z, S15 * x * y);
        float4 yb1 = make_float4(S15 * y * z, 1.118033988749895f * (3.f * z * z - 1.f),
                                 S15 * x * z, 0.5f * S15 * (x * x - y * y));
        if (q == 1) {
            *reinterpret_cast<float4*>(g_y + (size_t)i1 * 8)     = yb0;
            *reinterpret_cast<float4*>(g_y + (size_t)i1 * 8 + 4) = yb1;
        }
    }

    const float SCL = 0.0009765625f;   // 0.125 (w4 norm) * (1/64) * 0.5 (EPS)
    const bool odd  = (q & 1);
    const int  col4 = (q >> 1) * 4;
    float* myMsg = g_msg + (size_t)(odd ? i1 : i0) * 192;

    // ---- layer 4: 3 segments, store u = C*h*SCL via lane-pair exchange ----
#pragma unroll
    for (int seg = 0; seg < 3; seg++) {
        mma_layer_reg(aH, aL, wHi4, wLo4, 200, seg * 64, C, lane);
#pragma unroll
        for (int nt = 0; nt < 8; nt++) {
            float uA0 = C[nt][0] * hA[nt].x * SCL;
            float uA1 = C[nt][1] * hA[nt].y * SCL;
            float uB0 = C[nt][2] * hB[nt].x * SCL;
            float uB1 = C[nt][3] * hB[nt].y * SCL;
            float s0 = odd ? uA0 : uB0;
            float s1 = odd ? uA1 : uB1;
            float r0 = __shfl_xor_sync(0xFFFFFFFFu, s0, 1);
            float r1 = __shfl_xor_sync(0xFFFFFFFFu, s1, 1);
            float w0 = odd ? r0 : uA0;
            float w1 = odd ? r1 : uA1;
            float w2 = odd ? uB0 : r0;
            float w3 = odd ? uB1 : r1;
            *reinterpret_cast<float4*>(myMsg + seg * 64 + nt * 8 + col4) =
                make_float4(w0, w1, w2, w3);
        }
    }
}

// ---------------- gather: warp-per-node CSR reduction ---------------------------
__global__ void __launch_bounds__(256) k_gather() {
    const int wid  = threadIdx.x >> 5;
    const int lane = threadIdx.x & 31;
    const int n    = blockIdx.x * 8 + wid;
    const int beg  = g_rowptr[n];
    const int end  = g_rowptr[n + 1];

    float a0[2] = {0.f, 0.f};
    float a1[2][3] = {};
    float a2[2][5] = {};

    for (int i = beg; i < end; i++) {
        const float* m = g_msg + (size_t)i * 192;
        float u00 = m[lane],       u01 = m[lane + 32];
        float u10 = m[64 + lane],  u11 = m[96 + lane];
        float u20 = m[128 + lane], u21 = m[160 + lane];
        float4 y0 = *reinterpret_cast<const float4*>(g_y + (size_t)i * 8);
        float4 y1 = *reinterpret_cast<const float4*>(g_y + (size_t)i * 8 + 4);
        a0[0] += u00; a0[1] += u01;
        a1[0][0] += u10 * y0.x; a1[1][0] += u11 * y0.x;
        a1[0][1] += u10 * y0.y; a1[1][1] += u11 * y0.y;
        a1[0][2] += u10 * y0.z; a1[1][2] += u11 * y0.z;
        a2[0][0] += u20 * y0.w; a2[1][0] += u21 * y0.w;
        a2[0][1] += u20 * y1.x; a2[1][1] += u21 * y1.x;
        a2[0][2] += u20 * y1.y; a2[1][2] += u21 * y1.y;
        a2[0][3] += u20 * y1.z; a2[1][3] += u21 * y1.z;
        a2[0][4] += u20 * y1.w; a2[1][4] += u21 * y1.w;
    }

    float* ag = g_agg + (size_t)n * 576;
    ag[lane] = a0[0]; ag[lane + 32] = a0[1];
#pragma unroll
    for (int p = 0; p < 3; p++) {
        ag[64 + p * 64 + lane]      = a1[0][p];
        ag[64 + p * 64 + lane + 32] = a1[1][p];
    }
#pragma unroll
    for (int p = 0; p < 5; p++) {
        ag[256 + p * 64 + lane]      = a2[0][p];
        ag[256 + p * 64 + lane + 32] = a2[1][p];
    }
}

// ---------------- tensor-core down-projection -----------------------------------
__global__ void __launch_bounds__(256) k_down(const float* __restrict__ w0,
                                              const float* __restrict__ w1,
                                              const float* __restrict__ w2,
                                              float* __restrict__ out) {
    __shared__ __align__(16) uint32_t sWd[2 * 2304];   // hi @0, lo @2304

    const int t    = threadIdx.x;
    const int warp = t >> 5;
    const int lane = t & 31;
    const int g = lane >> 2, q = lane & 3;
    const int seg = blockIdx.y;
    const int nplanes = (seg == 0) ? 1 : (seg == 1 ? 3 : 5);
    const int stride  = nplanes;
    const int roff    = (seg == 0) ? 0 : (seg == 1 ? 64 : 256);
    const int woff    = (seg == 0) ? 0 : (seg == 1 ? 64 : 256);
    const float* W    = (seg == 0) ? w0 : (seg == 1 ? w1 : w2);

    for (int i = t; i < 2048; i += 256) {
        int k2 = i >> 6, n = i & 63;
        uint2 p = split_pair(W[(2 * k2) * 64 + n], W[(2 * k2 + 1) * 64 + n]);
        sWd[k2 * 72 + n] = p.x;
        sWd[2304 + k2 * 72 + n] = p.y;
    }
    __syncthreads();

    const int row0 = blockIdx.x * 128 + warp * 16 + g;
    const int row1 = row0 + 8;
    const bool ok0 = (row0 < N_NODES), ok1 = (row1 < N_NODES);

    for (int p = 0; p < nplanes; p++) {
        uint32_t aH[16], aL[16];
        const float* b0 = g_agg + (size_t)(ok0 ? row0 : 0) * 576 + roff + p * 64;
        const float* b1 = g_agg + (size_t)(ok1 ? row1 : 0) * 576 + roff + p * 64;
#pragma unroll
        for (int kt = 0; kt < 4; kt++) {
            float2 f0 = *reinterpret_cast<const float2*>(b0 + kt * 16 + 2 * q);
            float2 f1 = *reinterpret_cast<const float2*>(b1 + kt * 16 + 2 * q);
            float2 f2 = *reinterpret_cast<const float2*>(b0 + kt * 16 + 8 + 2 * q);
            float2 f3 = *reinterpret_cast<const float2*>(b1 + kt * 16 + 8 + 2 * q);
            uint2 p0 = split_pair(f0.x, f0.y);
            uint2 p1 = split_pair(f1.x, f1.y);
            uint2 p2 = split_pair(f2.x, f2.y);
            uint2 p3 = split_pair(f3.x, f3.y);
            aH[kt * 4 + 0] = p0.x; aL[kt * 4 + 0] = p0.y;
            aH[kt * 4 + 1] = p1.x; aL[kt * 4 + 1] = p1.y;
            aH[kt * 4 + 2] = p2.x; aL[kt * 4 + 2] = p2.y;
            aH[kt * 4 + 3] = p3.x; aL[kt * 4 + 3] = p3.y;
        }

        float C[8][4];
        mma_layer_reg(aH, aL, sWd, sWd + 2304, 72, 0, C, lane);

#pragma unroll
        for (int nt = 0; nt < 8; nt++) {
            const int col = nt * 8 + 2 * q;
            if (ok0) {
                out[(size_t)row0 * 576 + woff + col * stride + p]       = C[nt][0] * 0.125f;
                out[(size_t)row0 * 576 + woff + (col + 1) * stride + p] = C[nt][1] * 0.125f;
            }
            if (ok1) {
                out[(size_t)row1 * 576 + woff + col * stride + p]       = C[nt][2] * 0.125f;
                out[(size_t)row1 * 576 + woff + (col + 1) * stride + p] = C[nt][3] * 0.125f;
            }
        }
    }
}

// ---------------- launcher ------------------------------------------------------
extern "C" void kernel_launch(void* const* d_in, const int* in_sizes, int n_in,
                              void* d_out, int out_size) {
    const float* vectors    = (const float*)d_in[0];
    const float* node_feats = (const float*)d_in[1];
    const float* radial     = (const float*)d_in[2];
    const int*   senders    = (const int*)  d_in[3];
    const int*   receivers  = (const int*)  d_in[4];
    const float* w_up       = (const float*)d_in[5];
    const float* mlp_w1     = (const float*)d_in[6];
    const float* mlp_w2     = (const float*)d_in[7];
    const float* mlp_w3     = (const float*)d_in[8];
    const float* mlp_w4     = (const float*)d_in[9];
    const float* w_down0    = (const float*)d_in[10];
    const float* w_down1    = (const float*)d_in[11];
    const float* w_down2    = (const float*)d_in[12];
    float* out = (float*)d_out;

    const int FUSED_SMEM = 22592 * 4;    // 90,368 B -> 2 CTAs/SM
    cudaFuncSetAttribute(k_fused, cudaFuncAttributeMaxDynamicSharedMemorySize, FUSED_SMEM);

    k_init<<<708, 256>>>(node_feats, w_up, mlp_w1, mlp_w2, mlp_w3, mlp_w4);
    k_hist<<<1250, 256>>>(receivers);
    k_scan<<<1, 1024>>>();
    k_rank<<<1250, 256>>>(receivers);
    k_fused<<<2500, 256, FUSED_SMEM>>>(radial, vectors, senders);
    k_gather<<<2500, 256>>>();
    k_down<<<dim3(157, 3), 256>>>(w_down0, w_down1, w_down2, out);
}